// round 6
// baseline (speedup 1.0000x reference)
#include <cuda_runtime.h>
#include <cstdint>

#define NB    131072
#define DC    1029
#define TT    1024
#define H1N   64
#define H2N   32
#define KTOT  1028
#define KC    32
#define NCH   33              // 33*32 = 1056 padded K
#define MT    128             // rows per CTA
#define NT    256             // 8 warps: 4 m-groups x 2 n-groups
#define NSTG  4
#define A_ST  16384           // 128 rows * 128B (swizzled row-major)
#define B_ST  8192            // pre-packed B frags
#define STG   (A_ST + B_ST)
#define SMEM_DYN (NSTG * STG) // 98304
#define H_STRIDE 68

__device__ float g_row_mean[TT];
__device__ __align__(16) float g_w1f[NCH * 2048];   // pre-packed, pre-swizzled tf32 B frags

// ---------------- helpers ----------------
__device__ __forceinline__ uint32_t tf32r(float f) {
    uint32_t u;
    asm("cvt.rna.tf32.f32 %0, %1;" : "=r"(u) : "f"(f));
    return u;
}
__device__ __forceinline__ void mma_tf32(float* d, const uint32_t* a, uint32_t b0, uint32_t b1) {
    asm volatile(
        "mma.sync.aligned.m16n8k8.row.col.f32.tf32.tf32.f32 "
        "{%0,%1,%2,%3}, {%4,%5,%6,%7}, {%8,%9}, {%0,%1,%2,%3};"
        : "+f"(d[0]), "+f"(d[1]), "+f"(d[2]), "+f"(d[3])
        : "r"(a[0]), "r"(a[1]), "r"(a[2]), "r"(a[3]), "r"(b0), "r"(b1));
}
__device__ __forceinline__ uint32_t smem_u32(const void* p) {
    uint32_t a;
    asm("{ .reg .u64 t; cvta.to.shared.u64 t, %1; cvt.u32.u64 %0, t; }" : "=r"(a) : "l"(p));
    return a;
}
__device__ __forceinline__ void cp4(uint32_t dst, const float* src) {
    asm volatile("cp.async.ca.shared.global [%0], [%1], 4;"
                 :: "r"(dst), "l"(__cvta_generic_to_global(src)) : "memory");
}
__device__ __forceinline__ void cp16(uint32_t dst, const float* src) {
    asm volatile("cp.async.ca.shared.global [%0], [%1], 16;"
                 :: "r"(dst), "l"(__cvta_generic_to_global(src)) : "memory");
}
__device__ __forceinline__ float lds32(uint32_t a) {
    float v;
    asm volatile("ld.shared.f32 %0, [%1];" : "=f"(v) : "r"(a));
    return v;
}

// ---------------- merged prep kernel (identical pack layout to R5) ----------------
__global__ void prep_kernel(const float* __restrict__ con, const float* __restrict__ w1) {
    if (blockIdx.x < TT) {
        int t = blockIdx.x;
        float s = 0.f;
        for (int j = threadIdx.x; j < TT; j += blockDim.x)
            s += con[(size_t)t * TT + j];
#pragma unroll
        for (int o = 16; o > 0; o >>= 1) s += __shfl_down_sync(0xffffffffu, s, o);
        __shared__ float red[8];
        if ((threadIdx.x & 31) == 0) red[threadIdx.x >> 5] = s;
        __syncthreads();
        if (threadIdx.x == 0) {
            float tot = 0.f;
#pragma unroll
            for (int w = 0; w < 8; w++) tot += red[w];
            g_row_mean[t] = tot * (1.0f / (float)TT);
        }
    } else {
        int idx = (blockIdx.x - TT) * blockDim.x + threadIdx.x;
        if (idx >= NCH * 2048) return;
        int ch = idx >> 11;
        int w  = idx & 2047;
        int g  = w >> 2, e = w & 3;
        int kt = g >> 7;
        int lane = (g >> 2) & 31;
        int s = g & 3;
        int i = s ^ (lane & 3) ^ ((lane >> 2) & 1);
        int nt = 2 * i + (e >> 1);
        int jj = e & 1;
        int k = ch * 32 + kt * 8 + (lane & 3) + jj * 4;
        int n = nt * 8 + (lane >> 2);
        float v = 0.f;
        if (k < 4)          v = w1[k * H1N + n];
        else if (k < KTOT)  v = w1[(k + 1) * H1N + n];
        g_w1f[idx] = __uint_as_float(tf32r(v));
    }
}

// ---------------- fused main kernel ----------------
__global__ __launch_bounds__(NT, 2)
void fused_mma(const float* __restrict__ x,
               const float* __restrict__ w1,
               const float* __restrict__ b1,
               const float* __restrict__ w2,
               const float* __restrict__ b2,
               const float* __restrict__ w3,
               const float* __restrict__ b3,
               float* __restrict__ out)
{
    extern __shared__ __align__(16) char smem[];
    __shared__ __align__(16) float s_w2[H1N * H2N];
    __shared__ float s_w14[H1N], s_b1[H1N], s_b2[H2N], s_w3[H2N];
    __shared__ float s_ceff[MT];
    __shared__ int   s_mi[MT];

    const uint32_t sdyn = smem_u32(smem);
    const int tid  = threadIdx.x;
    const int w    = tid >> 5;
    const int lane = tid & 31;
    const int mg   = w & 3;        // m-group: rows mg*32..+31
    const int ng   = w >> 2;       // n-group: cols ng*32..+31
    const int rA   = lane >> 2;    // 0..7
    const int cA   = lane & 3;
    const int row0 = blockIdx.x * MT;

    // stage constants
#pragma unroll
    for (int i = tid; i < H1N * H2N; i += NT) s_w2[i] = __ldg(w2 + i);
    if (tid < H1N) { s_w14[tid] = __ldg(w1 + 4 * H1N + tid); s_b1[tid] = __ldg(b1 + tid); }
    if (tid < H2N) { s_b2[tid] = __ldg(b2 + tid); s_w3[tid] = __ldg(w3 + tid); }

    // ---- producer: A (coalesced cp4 + XOR swizzle) and B (cp16) ----
    auto produce = [&](int ch) {
        if (ch < NCH) {
            const uint32_t slot = sdyn + (uint32_t)(ch & (NSTG - 1)) * STG;
            const int kb = ch * KC;
#pragma unroll
            for (int i = 0; i < 16; i++) {
                const int idx = i * NT + tid;
                const int rl = idx >> 5;
                const int c4 = idx & 31;
                const int kg = kb + c4;
                if (kg < KTOT) {
                    const uint32_t d = slot + (uint32_t)rl * 128u
                                     + (uint32_t)((((c4 >> 2) ^ (rl & 7)) << 4) | ((c4 & 3) << 2));
                    cp4(d, x + (size_t)(row0 + rl) * DC + kg);
                }
            }
            const float* src = g_w1f + (size_t)ch * 2048;
            cp16(slot + A_ST + (uint32_t)tid * 16u, src + (size_t)tid * 4);
            cp16(slot + A_ST + (uint32_t)(tid + NT) * 16u, src + (size_t)(tid + NT) * 4);
        }
        asm volatile("cp.async.commit_group;" ::: "memory");
    };

    float amv[2];
    int   ami[2];
    amv[0] = amv[1] = __int_as_float(0xff800000);
    ami[0] = ami[1] = 0;

    float acc[2][4][4];
#pragma unroll
    for (int mt = 0; mt < 2; mt++)
#pragma unroll
        for (int nt = 0; nt < 4; nt++)
#pragma unroll
            for (int j = 0; j < 4; j++) acc[mt][nt][j] = 0.f;

    produce(0);
    produce(1);
    produce(2);

    for (int ch = 0; ch < NCH; ++ch) {
        asm volatile("cp.async.wait_group 2;" ::: "memory");
        __syncthreads();

        produce(ch + 3);

        const uint32_t slotA = sdyn + (uint32_t)(ch & (NSTG - 1)) * STG;
        const uint32_t slotB = slotA + A_ST;
        const int kb = ch * KC;

#pragma unroll
        for (int kt = 0; kt < 4; kt++) {
            // ---- A fragments: conflict-free LDS.32 ----
            float av[2][4];
            uint32_t au[2][4];
#pragma unroll
            for (int mt = 0; mt < 2; mt++) {
                const int r = mg * 32 + mt * 16 + rA;
                const uint32_t base = slotA + (uint32_t)r * 128u + (uint32_t)(cA << 2);
                const uint32_t a0 = base + (uint32_t)(((2 * kt) ^ rA) << 4);
                const uint32_t a2 = base + (uint32_t)(((2 * kt + 1) ^ rA) << 4);
                av[mt][0] = lds32(a0);
                av[mt][1] = lds32(a0 + 1024u);
                av[mt][2] = lds32(a2);
                av[mt][3] = lds32(a2 + 1024u);
            }

            // ---- argmax: this warp owns rows with parity ng ----
#pragma unroll
            for (int mt = 0; mt < 2; mt++)
#pragma unroll
                for (int h = 0; h < 2; h++) {
                    const float v = av[mt][h * 2 + ng];
                    const int kg = kb + kt * 8 + cA + 4 * h;
                    if ((unsigned)(kg - 4) < 1024u && v > amv[mt]) {
                        amv[mt] = v; ami[mt] = kg - 4;
                    }
                }

#pragma unroll
            for (int mt = 0; mt < 2; mt++)
#pragma unroll
                for (int j = 0; j < 4; j++) au[mt][j] = tf32r(av[mt][j]);

            // ---- B (this warp's n-half) + 8 MMAs ----
#pragma unroll
            for (int ii = 0; ii < 2; ii++) {
                const int i = 2 * ng + ii;
                const int s = i ^ cA ^ (rA & 1);
                uint4 q;
                const uint32_t baddr = slotB + (uint32_t)kt * 2048u
                                     + (uint32_t)lane * 64u + (uint32_t)(s << 4);
                asm volatile("ld.shared.v4.u32 {%0,%1,%2,%3}, [%4];"
                             : "=r"(q.x), "=r"(q.y), "=r"(q.z), "=r"(q.w) : "r"(baddr));
                mma_tf32(acc[0][2 * ii + 0], au[0], q.x, q.y);
                mma_tf32(acc[0][2 * ii + 1], au[0], q.z, q.w);
                mma_tf32(acc[1][2 * ii + 0], au[1], q.x, q.y);
                mma_tf32(acc[1][2 * ii + 1], au[1], q.z, q.w);
            }
        }
    }

    // ---- argmax reduce across the 4 cA lanes ----
    __syncthreads();
#pragma unroll
    for (int d = 1; d < 4; d <<= 1) {
#pragma unroll
        for (int mt = 0; mt < 2; mt++) {
            float ov = __shfl_xor_sync(0xffffffffu, amv[mt], d);
            int   oi = __shfl_xor_sync(0xffffffffu, ami[mt], d);
            if (ov > amv[mt] || (ov == amv[mt] && oi < ami[mt])) { amv[mt] = ov; ami[mt] = oi; }
        }
    }
    if (cA == 0) {
#pragma unroll
        for (int mt = 0; mt < 2; mt++)
            s_mi[mg * 32 + mt * 16 + rA + 8 * ng] = ami[mt];
    }
    __syncthreads();
    if (tid < MT)
        s_ceff[tid] = g_row_mean[s_mi[tid]] * __ldg(x + (size_t)(row0 + tid) * DC);
    __syncthreads();

    // ---- layer-1 epilogue: +ceff*w1[4,:]+b1, relu; h -> dynamic smem ----
    float* h = (float*)smem;
    {
#pragma unroll
        for (int mt = 0; mt < 2; mt++) {
            const int r1 = mg * 32 + mt * 16 + rA;
            const float ce0 = s_ceff[r1];
            const float ce1 = s_ceff[r1 + 8];
#pragma unroll
            for (int nt = 0; nt < 4; nt++) {
                const int c = ng * 32 + nt * 8 + cA * 2;
                const float w0 = s_w14[c], w1v = s_w14[c + 1];
                const float q0 = s_b1[c],  q1  = s_b1[c + 1];
                float2 top, bot;
                top.x = fmaxf(acc[mt][nt][0] + ce0 * w0 + q0, 0.f);
                top.y = fmaxf(acc[mt][nt][1] + ce0 * w1v + q1, 0.f);
                bot.x = fmaxf(acc[mt][nt][2] + ce1 * w0 + q0, 0.f);
                bot.y = fmaxf(acc[mt][nt][3] + ce1 * w1v + q1, 0.f);
                *reinterpret_cast<float2*>(h + (size_t)r1 * H_STRIDE + c) = top;
                *reinterpret_cast<float2*>(h + (size_t)(r1 + 8) * H_STRIDE + c) = bot;
            }
        }
    }
    __syncthreads();

    // ---- layers 2 & 3: one thread per row ----
    if (tid < MT) {
        float a2[H2N];
#pragma unroll
        for (int j = 0; j < H2N; j++) a2[j] = s_b2[j];
        const float* hr = h + (size_t)tid * H_STRIDE;
#pragma unroll 4
        for (int k = 0; k < H1N; k++) {
            const float a = hr[k];
            const float4* w2r = reinterpret_cast<const float4*>(s_w2 + k * H2N);
#pragma unroll
            for (int qq = 0; qq < H2N / 4; qq++) {
                float4 w4 = w2r[qq];
                a2[qq * 4 + 0] += a * w4.x;
                a2[qq * 4 + 1] += a * w4.y;
                a2[qq * 4 + 2] += a * w4.z;
                a2[qq * 4 + 3] += a * w4.w;
            }
        }
        float o = __ldg(b3);
#pragma unroll
        for (int j = 0; j < H2N; j++)
            o += fmaxf(a2[j], 0.f) * s_w3[j];
        out[row0 + tid] = fmaxf(o, 0.f);
    }
}

// ---------------- launch (2 launches per call) ----------------
extern "C" void kernel_launch(void* const* d_in, const int* in_sizes, int n_in,
                              void* d_out, int out_size) {
    const float* x   = (const float*)d_in[0];
    const float* con = (const float*)d_in[1];
    const float* w1  = (const float*)d_in[2];
    const float* b1  = (const float*)d_in[3];
    const float* w2  = (const float*)d_in[4];
    const float* b2  = (const float*)d_in[5];
    const float* w3  = (const float*)d_in[6];
    const float* b3  = (const float*)d_in[7];
    float* out = (float*)d_out;

    cudaFuncSetAttribute(fused_mma, cudaFuncAttributeMaxDynamicSharedMemorySize, SMEM_DYN);

    prep_kernel<<<TT + (NCH * 2048 + 255) / 256, 256>>>(con, w1);
    fused_mma<<<NB / MT, NT, SMEM_DYN>>>(x, w1, b1, w2, b2, w3, b3, out);
}

// round 7
// speedup vs baseline: 1.5618x; 1.5618x over previous
#include <cuda_runtime.h>
#include <cstdint>

#define NB    131072
#define DC    1029
#define TT    1024
#define H1N   64
#define H2N   32
#define KTOT  1028
#define KC    32
#define NCH   33              // 33*32 = 1056 padded K
#define MT    128             // rows per CTA
#define NT    256             // 8 warps: 4 m-groups x 2 n-groups
#define NSTG  4
#define A_SLOT 16384          // 128 rows * 128B, raw f32, swizzled
#define B_OFF  32768          // A ring = 2 slots
#define B_ST   8192
#define SMEM_DYN 65536        // 2*A_SLOT + 4*B_ST
#define H_STRIDE 68

__device__ float g_row_mean[TT];
__device__ __align__(16) float g_w1f[NCH * 2048];   // pre-packed, pre-swizzled tf32 B frags

// ---------------- helpers ----------------
__device__ __forceinline__ uint32_t tf32r(float f) {
    uint32_t u;
    asm("cvt.rna.tf32.f32 %0, %1;" : "=r"(u) : "f"(f));
    return u;
}
__device__ __forceinline__ void mma_tf32(float* d, const uint32_t* a, uint32_t b0, uint32_t b1) {
    asm volatile(
        "mma.sync.aligned.m16n8k8.row.col.f32.tf32.tf32.f32 "
        "{%0,%1,%2,%3}, {%4,%5,%6,%7}, {%8,%9}, {%0,%1,%2,%3};"
        : "+f"(d[0]), "+f"(d[1]), "+f"(d[2]), "+f"(d[3])
        : "r"(a[0]), "r"(a[1]), "r"(a[2]), "r"(a[3]), "r"(b0), "r"(b1));
}
__device__ __forceinline__ uint32_t smem_u32(const void* p) {
    uint32_t a;
    asm("{ .reg .u64 t; cvta.to.shared.u64 t, %1; cvt.u32.u64 %0, t; }" : "=r"(a) : "l"(p));
    return a;
}
__device__ __forceinline__ void cp16(uint32_t dst, const float* src) {
    asm volatile("cp.async.ca.shared.global [%0], [%1], 16;"
                 :: "r"(dst), "l"(__cvta_generic_to_global(src)) : "memory");
}
__device__ __forceinline__ float lds32(uint32_t a) {
    float v;
    asm volatile("ld.shared.f32 %0, [%1];" : "=f"(v) : "r"(a));
    return v;
}

// ---------------- merged prep kernel (identical pack layout to R5/R6) ----------------
__global__ void prep_kernel(const float* __restrict__ con, const float* __restrict__ w1) {
    if (blockIdx.x < TT) {
        int t = blockIdx.x;
        float s = 0.f;
        for (int j = threadIdx.x; j < TT; j += blockDim.x)
            s += con[(size_t)t * TT + j];
#pragma unroll
        for (int o = 16; o > 0; o >>= 1) s += __shfl_down_sync(0xffffffffu, s, o);
        __shared__ float red[8];
        if ((threadIdx.x & 31) == 0) red[threadIdx.x >> 5] = s;
        __syncthreads();
        if (threadIdx.x == 0) {
            float tot = 0.f;
#pragma unroll
            for (int w = 0; w < 8; w++) tot += red[w];
            g_row_mean[t] = tot * (1.0f / (float)TT);
        }
    } else {
        int idx = (blockIdx.x - TT) * blockDim.x + threadIdx.x;
        if (idx >= NCH * 2048) return;
        int ch = idx >> 11;
        int w  = idx & 2047;
        int g  = w >> 2, e = w & 3;
        int kt = g >> 7;
        int lane = (g >> 2) & 31;
        int s = g & 3;
        int i = s ^ (lane & 3) ^ ((lane >> 2) & 1);
        int nt = 2 * i + (e >> 1);
        int jj = e & 1;
        int k = ch * 32 + kt * 8 + (lane & 3) + jj * 4;
        int n = nt * 8 + (lane >> 2);
        float v = 0.f;
        if (k < 4)          v = w1[k * H1N + n];
        else if (k < KTOT)  v = w1[(k + 1) * H1N + n];
        g_w1f[idx] = __uint_as_float(tf32r(v));
    }
}

// ---------------- fused main kernel ----------------
__global__ __launch_bounds__(NT, 2)
void fused_mma(const float* __restrict__ x,
               const float* __restrict__ w1,
               const float* __restrict__ b1,
               const float* __restrict__ w2,
               const float* __restrict__ b2,
               const float* __restrict__ w3,
               const float* __restrict__ b3,
               float* __restrict__ out)
{
    extern __shared__ __align__(128) char smem[];
    __shared__ __align__(16) float s_w2[H1N * H2N];
    __shared__ float s_w14[H1N], s_b1[H1N], s_b2[H2N], s_w3[H2N];
    __shared__ float s_ceff[MT];
    __shared__ int   s_mi[MT];

    const uint32_t sdyn = smem_u32(smem);
    const int tid  = threadIdx.x;
    const int w    = tid >> 5;
    const int lane = tid & 31;
    const int mg   = w >> 1;       // m-group: rows mg*32..+31
    const int ng   = w & 1;        // n-group: cols ng*32..+31
    const int rA   = lane >> 2;
    const int cA   = lane & 3;
    const int row0 = blockIdx.x * MT;

    // stage constants
#pragma unroll
    for (int i = tid; i < H1N * H2N; i += NT) s_w2[i] = __ldg(w2 + i);
    if (tid < H1N) { s_w14[tid] = __ldg(w1 + 4 * H1N + tid); s_b1[tid] = __ldg(b1 + tid); }
    if (tid < H2N) { s_b2[tid] = __ldg(b2 + tid); s_w3[tid] = __ldg(w3 + tid); }

    // ---- A producer: warp w owns rows w*16..+15, lane = column ----
    float pre[16];
    const float* xw = x + (size_t)(row0 + w * 16) * DC + lane;

    auto ldgA = [&](int ch) {
        if (ch >= NCH) return;
        const int kb = ch * KC;
        const bool ok = (kb + lane) < KTOT;
#pragma unroll
        for (int r = 0; r < 16; r++)
            pre[r] = ok ? __ldg(xw + (size_t)r * DC + kb) : 0.f;
    };
    auto stsA = [&](int ch) {
        const uint32_t slot = sdyn + (uint32_t)(ch & 1) * A_SLOT;
        const int g = lane >> 2;
        const uint32_t coff = (uint32_t)(cA << 2);
#pragma unroll
        for (int r = 0; r < 16; r++) {
            const int rr = w * 16 + r;
            const uint32_t addr = slot + (uint32_t)rr * 128u
                                + (uint32_t)((g ^ (rr & 7)) << 4) + coff;
            asm volatile("st.shared.f32 [%0], %1;" :: "r"(addr), "f"(pre[r]));
        }
    };

    // ---- B producer: cp.async ring (pre-packed frags, identity copy) ----
    auto produceB = [&](int ch) {
        if (ch < NCH) {
            const uint32_t slot = sdyn + B_OFF + (uint32_t)(ch & (NSTG - 1)) * B_ST;
            const float* src = g_w1f + (size_t)ch * 2048;
            cp16(slot + (uint32_t)tid * 16u, src + (size_t)tid * 4);
            cp16(slot + (uint32_t)(tid + NT) * 16u, src + (size_t)(tid + NT) * 4);
        }
        asm volatile("cp.async.commit_group;" ::: "memory");
    };

    float amv[2];
    int   ami[2];
    amv[0] = amv[1] = __int_as_float(0xff800000);
    ami[0] = ami[1] = 0;

    float acc[2][4][4];
#pragma unroll
    for (int mt = 0; mt < 2; mt++)
#pragma unroll
        for (int nt = 0; nt < 4; nt++)
#pragma unroll
            for (int j = 0; j < 4; j++) acc[mt][nt][j] = 0.f;

    // prologue
    produceB(0);
    produceB(1);
    produceB(2);
    ldgA(0);
    stsA(0);
    ldgA(1);

    for (int ch = 0; ch < NCH; ++ch) {
        asm volatile("cp.async.wait_group 2;" ::: "memory");
        __syncthreads();              // A(ch) + B(ch) visible

        produceB(ch + 3);
        if (ch + 1 < NCH) {
            stsA(ch + 1);             // regs -> other A slot (not read until next sync)
            ldgA(ch + 2);             // prefetch, full chunk of latency cover
        }

        const uint32_t slotA = sdyn + (uint32_t)(ch & 1) * A_SLOT;
        const uint32_t slotB = sdyn + B_OFF + (uint32_t)(ch & 3) * B_ST;
        const int kb = ch * KC;

#pragma unroll
        for (int kt = 0; kt < 4; kt++) {
            float av[2][4];
            uint32_t au[2][4];
#pragma unroll
            for (int mt = 0; mt < 2; mt++) {
                const int r = mg * 32 + mt * 16 + rA;
                const uint32_t base = slotA + (uint32_t)r * 128u + (uint32_t)(cA << 2);
                const uint32_t a0 = base + (uint32_t)(((2 * kt) ^ rA) << 4);
                const uint32_t a2 = base + (uint32_t)(((2 * kt + 1) ^ rA) << 4);
                av[mt][0] = lds32(a0);
                av[mt][1] = lds32(a0 + 1024u);
                av[mt][2] = lds32(a2);
                av[mt][3] = lds32(a2 + 1024u);
            }

            // argmax on raw f32; warp owns rows rA + 8*ng (+16*mt) within its m-group
#pragma unroll
            for (int mt = 0; mt < 2; mt++)
#pragma unroll
                for (int h = 0; h < 2; h++) {
                    const float v = av[mt][h * 2 + ng];
                    const int kg = kb + kt * 8 + cA + 4 * h;
                    if ((unsigned)(kg - 4) < 1024u && v > amv[mt]) {
                        amv[mt] = v; ami[mt] = kg - 4;
                    }
                }

#pragma unroll
            for (int mt = 0; mt < 2; mt++)
#pragma unroll
                for (int j = 0; j < 4; j++) au[mt][j] = tf32r(av[mt][j]);

#pragma unroll
            for (int ii = 0; ii < 2; ii++) {
                const int i = 2 * ng + ii;
                const int s = i ^ cA ^ (rA & 1);
                uint4 q;
                const uint32_t baddr = slotB + (uint32_t)kt * 2048u
                                     + (uint32_t)lane * 64u + (uint32_t)(s << 4);
                asm volatile("ld.shared.v4.u32 {%0,%1,%2,%3}, [%4];"
                             : "=r"(q.x), "=r"(q.y), "=r"(q.z), "=r"(q.w) : "r"(baddr));
                mma_tf32(acc[0][2 * ii + 0], au[0], q.x, q.y);
                mma_tf32(acc[0][2 * ii + 1], au[0], q.z, q.w);
                mma_tf32(acc[1][2 * ii + 0], au[1], q.x, q.y);
                mma_tf32(acc[1][2 * ii + 1], au[1], q.z, q.w);
            }
        }
    }

    // ---- argmax reduce across the 4 cA lanes ----
    __syncthreads();
#pragma unroll
    for (int d = 1; d < 4; d <<= 1) {
#pragma unroll
        for (int mt = 0; mt < 2; mt++) {
            float ov = __shfl_xor_sync(0xffffffffu, amv[mt], d);
            int   oi = __shfl_xor_sync(0xffffffffu, ami[mt], d);
            if (ov > amv[mt] || (ov == amv[mt] && oi < ami[mt])) { amv[mt] = ov; ami[mt] = oi; }
        }
    }
    if (cA == 0) {
#pragma unroll
        for (int mt = 0; mt < 2; mt++)
            s_mi[mg * 32 + mt * 16 + rA + 8 * ng] = ami[mt];
    }
    __syncthreads();
    if (tid < MT)
        s_ceff[tid] = g_row_mean[s_mi[tid]] * __ldg(x + (size_t)(row0 + tid) * DC);
    __syncthreads();

    // ---- layer-1 epilogue: +ceff*w1[4,:]+b1, relu; h -> dynamic smem ----
    float* h = (float*)smem;
    {
#pragma unroll
        for (int mt = 0; mt < 2; mt++) {
            const int r1 = mg * 32 + mt * 16 + rA;
            const float ce0 = s_ceff[r1];
            const float ce1 = s_ceff[r1 + 8];
#pragma unroll
            for (int nt = 0; nt < 4; nt++) {
                const int c = ng * 32 + nt * 8 + cA * 2;
                const float w0 = s_w14[c], w1v = s_w14[c + 1];
                const float q0 = s_b1[c],  q1  = s_b1[c + 1];
                float2 top, bot;
                top.x = fmaxf(acc[mt][nt][0] + ce0 * w0 + q0, 0.f);
                top.y = fmaxf(acc[mt][nt][1] + ce0 * w1v + q1, 0.f);
                bot.x = fmaxf(acc[mt][nt][2] + ce1 * w0 + q0, 0.f);
                bot.y = fmaxf(acc[mt][nt][3] + ce1 * w1v + q1, 0.f);
                *reinterpret_cast<float2*>(h + (size_t)r1 * H_STRIDE + c) = top;
                *reinterpret_cast<float2*>(h + (size_t)(r1 + 8) * H_STRIDE + c) = bot;
            }
        }
    }
    __syncthreads();

    // ---- layers 2 & 3: one thread per row ----
    if (tid < MT) {
        float a2[H2N];
#pragma unroll
        for (int j = 0; j < H2N; j++) a2[j] = s_b2[j];
        const float* hr = h + (size_t)tid * H_STRIDE;
#pragma unroll 4
        for (int k = 0; k < H1N; k++) {
            const float a = hr[k];
            const float4* w2r = reinterpret_cast<const float4*>(s_w2 + k * H2N);
#pragma unroll
            for (int qq = 0; qq < H2N / 4; qq++) {
                float4 w4 = w2r[qq];
                a2[qq * 4 + 0] += a * w4.x;
                a2[qq * 4 + 1] += a * w4.y;
                a2[qq * 4 + 2] += a * w4.z;
                a2[qq * 4 + 3] += a * w4.w;
            }
        }
        float o = __ldg(b3);
#pragma unroll
        for (int j = 0; j < H2N; j++)
            o += fmaxf(a2[j], 0.f) * s_w3[j];
        out[row0 + tid] = fmaxf(o, 0.f);
    }
}

// ---------------- launch (2 launches per call) ----------------
extern "C" void kernel_launch(void* const* d_in, const int* in_sizes, int n_in,
                              void* d_out, int out_size) {
    const float* x   = (const float*)d_in[0];
    const float* con = (const float*)d_in[1];
    const float* w1  = (const float*)d_in[2];
    const float* b1  = (const float*)d_in[3];
    const float* w2  = (const float*)d_in[4];
    const float* b2  = (const float*)d_in[5];
    const float* w3  = (const float*)d_in[6];
    const float* b3  = (const float*)d_in[7];
    float* out = (float*)d_out;

    cudaFuncSetAttribute(fused_mma, cudaFuncAttributeMaxDynamicSharedMemorySize, SMEM_DYN);

    prep_kernel<<<TT + (NCH * 2048 + 255) / 256, 256>>>(con, w1);
    fused_mma<<<NB / MT, NT, SMEM_DYN>>>(x, w1, b1, w2, b2, w3, b3, out);
}

// round 8
// speedup vs baseline: 1.6167x; 1.0351x over previous
#include <cuda_runtime.h>
#include <cstdint>

#define NB    131072
#define DC    1029
#define TT    1024
#define H1N   64
#define H2N   32
#define KTOT  1028
#define KC    32
#define NCH   33              // 33*32 = 1056 padded K
#define MT    128             // rows per CTA
#define NT    256             // 8 warps, each m16 x n64
#define H_STRIDE 68

__device__ float g_row_mean[TT];
__device__ __align__(16) float g_w1f[NCH * 2048];   // pre-packed tf32 B frags (LDG.128 layout)

// ---------------- helpers ----------------
__device__ __forceinline__ uint32_t tf32r(float f) {
    uint32_t u;
    asm("cvt.rna.tf32.f32 %0, %1;" : "=r"(u) : "f"(f));
    return u;
}
__device__ __forceinline__ void mma_tf32(float* d, const uint32_t* a, uint32_t b0, uint32_t b1) {
    asm volatile(
        "mma.sync.aligned.m16n8k8.row.col.f32.tf32.tf32.f32 "
        "{%0,%1,%2,%3}, {%4,%5,%6,%7}, {%8,%9}, {%0,%1,%2,%3};"
        : "+f"(d[0]), "+f"(d[1]), "+f"(d[2]), "+f"(d[3])
        : "r"(a[0]), "r"(a[1]), "r"(a[2]), "r"(a[3]), "r"(b0), "r"(b1));
}

// ---------------- merged prep kernel ----------------
// blocks [0, TT): contention row means.
// blocks [TT, ..): pack B frags for direct LDG.128:
//   granule g = w>>2 (16B), elem e = w&3
//   kt = g>>7, i = (g>>5)&3, lane = g&31
//   nt = 2*i + (e>>1), jj = e&1
//   value = Bshift[k = ch*32 + kt*8 + (lane&3) + jj*4][n = nt*8 + (lane>>2)]
__global__ void prep_kernel(const float* __restrict__ con, const float* __restrict__ w1) {
    if (blockIdx.x < TT) {
        int t = blockIdx.x;
        float s = 0.f;
        for (int j = threadIdx.x; j < TT; j += blockDim.x)
            s += con[(size_t)t * TT + j];
#pragma unroll
        for (int o = 16; o > 0; o >>= 1) s += __shfl_down_sync(0xffffffffu, s, o);
        __shared__ float red[8];
        if ((threadIdx.x & 31) == 0) red[threadIdx.x >> 5] = s;
        __syncthreads();
        if (threadIdx.x == 0) {
            float tot = 0.f;
#pragma unroll
            for (int w = 0; w < 8; w++) tot += red[w];
            g_row_mean[t] = tot * (1.0f / (float)TT);
        }
    } else {
        int idx = (blockIdx.x - TT) * blockDim.x + threadIdx.x;
        if (idx >= NCH * 2048) return;
        int ch = idx >> 11;
        int w  = idx & 2047;
        int g  = w >> 2, e = w & 3;
        int kt   = g >> 7;
        int i    = (g >> 5) & 3;
        int lane = g & 31;
        int nt = 2 * i + (e >> 1);
        int jj = e & 1;
        int k = ch * 32 + kt * 8 + (lane & 3) + jj * 4;
        int n = nt * 8 + (lane >> 2);
        float v = 0.f;
        if (k < 4)          v = w1[k * H1N + n];
        else if (k < KTOT)  v = w1[(k + 1) * H1N + n];
        g_w1f[idx] = __uint_as_float(tf32r(v));
    }
}

// ---------------- fused main kernel (no smem, no syncs in main loop) ----------------
__global__ __launch_bounds__(NT, 2)
void fused_mma(const float* __restrict__ x,
               const float* __restrict__ w1,
               const float* __restrict__ b1,
               const float* __restrict__ w2,
               const float* __restrict__ b2,
               const float* __restrict__ w3,
               const float* __restrict__ b3,
               float* __restrict__ out)
{
    __shared__ __align__(16) float h[MT * H_STRIDE];
    __shared__ __align__(16) float s_w2[H1N * H2N];
    __shared__ float s_w14[H1N], s_b1[H1N], s_b2[H2N], s_w3[H2N];
    __shared__ float s_den[MT], s_ceff[MT];
    __shared__ int   s_mi[MT];

    const int tid  = threadIdx.x;
    const int w    = tid >> 5;
    const int lane = tid & 31;
    const int rA   = lane >> 2;
    const int cA   = lane & 3;
    const int row0 = blockIdx.x * MT;

    // stage constants
#pragma unroll
    for (int i = tid; i < H1N * H2N; i += NT) s_w2[i] = __ldg(w2 + i);
    if (tid < H1N) { s_w14[tid] = __ldg(w1 + 4 * H1N + tid); s_b1[tid] = __ldg(b1 + tid); }
    if (tid < H2N) { s_b2[tid] = __ldg(b2 + tid); s_w3[tid] = __ldg(w3 + tid); }

    // A loader: 16 floats in fragment layout (idx = kt*4 + h*2 + r)
    const float* xp0 = x + (size_t)(row0 + w * 16 + rA) * DC + cA;
    const float* xp1 = xp0 + 8 * (size_t)DC;
    auto loadA = [&](int ch, float* dst) {
        const int kb = ch * KC;
#pragma unroll
        for (int kt = 0; kt < 4; kt++)
#pragma unroll
            for (int hh = 0; hh < 2; hh++) {
                const int kg = kb + kt * 8 + hh * 4;          // + cA baked into pointer
                const bool ok = (kg + cA) < KTOT;
                dst[kt * 4 + hh * 2 + 0] = ok ? __ldg(xp0 + kg) : 0.f;
                dst[kt * 4 + hh * 2 + 1] = ok ? __ldg(xp1 + kg) : 0.f;
            }
    };

    float amv[2];
    int   ami[2];
    amv[0] = amv[1] = __int_as_float(0xff800000);
    ami[0] = ami[1] = 0;

    float acc[8][4];
#pragma unroll
    for (int nt = 0; nt < 8; nt++)
#pragma unroll
        for (int j = 0; j < 4; j++) acc[nt][j] = 0.f;

    float cur[16], nxt[16];
    loadA(0, cur);

    const float4* Bg = reinterpret_cast<const float4*>(g_w1f) + lane;  // + chunk/kt/i offsets

    for (int ch = 0; ch < NCH; ++ch) {
        if (ch + 1 < NCH) loadA(ch + 1, nxt);    // register prefetch, deep MLP

        // argmax + density on raw f32 (each x element owned by exactly one thread)
        const int kb = ch * KC;
#pragma unroll
        for (int kt = 0; kt < 4; kt++)
#pragma unroll
            for (int hh = 0; hh < 2; hh++) {
                const int kg = kb + kt * 8 + cA + hh * 4;
                const float v0 = cur[kt * 4 + hh * 2 + 0];
                const float v1 = cur[kt * 4 + hh * 2 + 1];
                if ((unsigned)(kg - 4) < 1024u) {
                    if (v0 > amv[0]) { amv[0] = v0; ami[0] = kg - 4; }
                    if (v1 > amv[1]) { amv[1] = v1; ami[1] = kg - 4; }
                }
            }
        if (ch == 0 && cA == 0) {
            s_den[w * 16 + rA]     = cur[0];
            s_den[w * 16 + rA + 8] = cur[1];
        }

        uint32_t au[16];
#pragma unroll
        for (int i = 0; i < 16; i++) au[i] = tf32r(cur[i]);

        // B fragments straight from global (L1/L2-resident), LDG.128
        const float4* Bc = Bg + (size_t)ch * 512;
#pragma unroll
        for (int kt = 0; kt < 4; kt++) {
            const uint32_t* a = au + kt * 4;
#pragma unroll
            for (int i = 0; i < 4; i++) {
                const float4 qf = __ldg(Bc + kt * 128 + i * 32);
                const uint32_t q0 = __float_as_uint(qf.x);
                const uint32_t q1 = __float_as_uint(qf.y);
                const uint32_t q2 = __float_as_uint(qf.z);
                const uint32_t q3 = __float_as_uint(qf.w);
                mma_tf32(acc[2 * i + 0], a, q0, q1);
                mma_tf32(acc[2 * i + 1], a, q2, q3);
            }
        }

#pragma unroll
        for (int i = 0; i < 16; i++) cur[i] = nxt[i];
    }

    // ---- argmax reduce across the 4 cA lanes ----
#pragma unroll
    for (int d = 1; d < 4; d <<= 1) {
#pragma unroll
        for (int hf = 0; hf < 2; hf++) {
            float ov = __shfl_xor_sync(0xffffffffu, amv[hf], d);
            int   oi = __shfl_xor_sync(0xffffffffu, ami[hf], d);
            if (ov > amv[hf] || (ov == amv[hf] && oi < ami[hf])) { amv[hf] = ov; ami[hf] = oi; }
        }
    }
    if (cA == 0) {
        s_mi[w * 16 + rA]     = ami[0];
        s_mi[w * 16 + rA + 8] = ami[1];
    }
    __syncthreads();
    if (tid < MT) s_ceff[tid] = g_row_mean[s_mi[tid]] * s_den[tid];
    __syncthreads();

    // ---- layer-1 epilogue: +ceff*w1[4,:]+b1, relu; h -> smem ----
    {
        const int r1 = w * 16 + rA;
        const int cb = cA * 2;
        const float ce0 = s_ceff[r1];
        const float ce1 = s_ceff[r1 + 8];
#pragma unroll
        for (int nt = 0; nt < 8; nt++) {
            const int c = nt * 8 + cb;
            const float w0 = s_w14[c], w1v = s_w14[c + 1];
            const float q0 = s_b1[c],  q1  = s_b1[c + 1];
            float2 top, bot;
            top.x = fmaxf(acc[nt][0] + ce0 * w0 + q0, 0.f);
            top.y = fmaxf(acc[nt][1] + ce0 * w1v + q1, 0.f);
            bot.x = fmaxf(acc[nt][2] + ce1 * w0 + q0, 0.f);
            bot.y = fmaxf(acc[nt][3] + ce1 * w1v + q1, 0.f);
            *reinterpret_cast<float2*>(h + (size_t)r1 * H_STRIDE + c) = top;
            *reinterpret_cast<float2*>(h + (size_t)(r1 + 8) * H_STRIDE + c) = bot;
        }
    }
    __syncthreads();

    // ---- layers 2 & 3: one thread per row ----
    if (tid < MT) {
        float a2[H2N];
#pragma unroll
        for (int j = 0; j < H2N; j++) a2[j] = s_b2[j];
        const float* hr = h + (size_t)tid * H_STRIDE;
#pragma unroll 4
        for (int k = 0; k < H1N; k++) {
            const float a = hr[k];
            const float4* w2r = reinterpret_cast<const float4*>(s_w2 + k * H2N);
#pragma unroll
            for (int qq = 0; qq < H2N / 4; qq++) {
                float4 w4 = w2r[qq];
                a2[qq * 4 + 0] += a * w4.x;
                a2[qq * 4 + 1] += a * w4.y;
                a2[qq * 4 + 2] += a * w4.z;
                a2[qq * 4 + 3] += a * w4.w;
            }
        }
        float o = __ldg(b3);
#pragma unroll
        for (int j = 0; j < H2N; j++)
            o += fmaxf(a2[j], 0.f) * s_w3[j];
        out[row0 + tid] = fmaxf(o, 0.f);
    }
}

// ---------------- launch (2 launches per call) ----------------
extern "C" void kernel_launch(void* const* d_in, const int* in_sizes, int n_in,
                              void* d_out, int out_size) {
    const float* x   = (const float*)d_in[0];
    const float* con = (const float*)d_in[1];
    const float* w1  = (const float*)d_in[2];
    const float* b1  = (const float*)d_in[3];
    const float* w2  = (const float*)d_in[4];
    const float* b2  = (const float*)d_in[5];
    const float* w3  = (const float*)d_in[6];
    const float* b3  = (const float*)d_in[7];
    float* out = (float*)d_out;

    prep_kernel<<<TT + (NCH * 2048 + 255) / 256, 256>>>(con, w1);
    fused_mma<<<NB / MT, NT>>>(x, w1, b1, w2, b2, w3, b3, out);
}